// round 3
// baseline (speedup 1.0000x reference)
#include <cuda_runtime.h>
#include <cuda_bf16.h>
#include <math_constants.h>

// Problem constants (fixed by the benchmark)
#define BB 2
#define LL 2048
#define HH 8
#define DD 64
#define UU 80
#define SS 80
#define BHN (BB*HH)
#define SPLIT 16
#define CHUNK (LL/SPLIT)      // 128 keys per split block
#define VSPLIT 8
#define VCHUNK (LL/VSPLIT)    // 256 keys per vmean split

// Sample-stage tiling
#define LT 128                // l rows per block
#define KT 256                // keys per smem tile
#define NT (LL/KT)            // 8 key tiles
#define KPAD 68               // padded row width (floats) for bank spread
#define SMP_SMEM ((LT*64 + KT*KPAD + 2*LT)*4)

// Scratch (device globals; no allocations allowed)
__device__ float g_M[BB*HH*LL];          // sparsity measure M[b,h,l]
__device__ int   g_sj[LL*SS];            // sample indices bucketed by key tile
__device__ int   g_soff[LL*(NT+1)];      // bucket offsets per l
__device__ int   g_nw[BHN];              // winners per (b,h)
__device__ int   g_wl[BHN*UU];           // winner: source token l
__device__ int   g_wj[BHN*UU];           // winner: output slot j
__device__ float g_pmax[BHN*UU*SPLIT];   // split-softmax partial max
__device__ float g_psum[BHN*UU*SPLIT];   // split-softmax partial sum(exp)
__device__ float g_pv  [BHN*UU*SPLIT*DD];// split partial (unnormalized) PV
__device__ float g_vpart[BHN*VSPLIT*DD]; // V partial sums

// ---------------------------------------------------------------------------
// Kernel 0: bucket each l-row's 80 sample indices by key tile (j >> 8).
// Shared across all (b,h). Order within a bucket keeps original s order.
// ---------------------------------------------------------------------------
__global__ void k_bucket(const int* __restrict__ idx) {
    int l = blockIdx.x * blockDim.x + threadIdx.x;
    if (l >= LL) return;
    const int* row = idx + l*SS;
    int cnt[NT];
    #pragma unroll
    for (int i = 0; i < NT; ++i) cnt[i] = 0;
    for (int s = 0; s < SS; ++s) cnt[row[s] >> 8]++;
    int off[NT+1]; off[0] = 0;
    #pragma unroll
    for (int i = 0; i < NT; ++i) off[i+1] = off[i] + cnt[i];
    #pragma unroll
    for (int i = 0; i <= NT; ++i) g_soff[l*(NT+1) + i] = off[i];
    for (int s = 0; s < SS; ++s) {
        int j = row[s];
        g_sj[l*SS + off[j >> 8]++] = j;
    }
}

// ---------------------------------------------------------------------------
// Kernel 1: sampled scores with SMEM-staged K tiles.
// Block = (l-tile, bh). Stages Q tile once, loops 8 K tiles of 256 rows.
// Warp owns 16 l rows; per l, 4 groups of 8 lanes do 4 sampled dots at a time
// (predicated for ragged bucket sizes, so the warp stays converged).
// ---------------------------------------------------------------------------
__global__ void k_sample2(const float* __restrict__ Q, const float* __restrict__ K) {
    extern __shared__ float dsm[];
    float* Qs   = dsm;                 // LT*64
    float* Ks   = dsm + LT*64;         // KT*KPAD
    float* smax = Ks + KT*KPAD;        // LT
    float* ssum = smax + LT;           // LT

    int bh = blockIdx.y; int b = bh >> 3, h = bh & 7;
    int l0 = blockIdx.x * LT;
    int t = threadIdx.x, lane = t & 31, warp = t >> 5;
    int grp = lane >> 3, lg = lane & 7;

    // stage Q tile (coalesced float4)
    #pragma unroll 4
    for (int e = t; e < LT*16; e += 256) {
        int li = e >> 4, d4 = e & 15;
        ((float4*)Qs)[li*16 + d4] =
            *(const float4*)(Q + (((size_t)b*LL + l0 + li)*HH + h)*DD + d4*4);
    }
    for (int i = t; i < LT; i += 256) { smax[i] = -CUDART_INF_F; ssum[i] = 0.f; }
    __syncthreads();

    for (int kt = 0; kt < NT; ++kt) {
        // stage K tile
        #pragma unroll 8
        for (int e = t; e < KT*16; e += 256) {
            int j = e >> 4, d4 = e & 15;
            float4 v = *(const float4*)(K + (((size_t)b*LL + kt*KT + j)*HH + h)*DD + d4*4);
            *(float4*)(Ks + j*KPAD + d4*4) = v;
        }
        __syncthreads();

        for (int li = warp*16; li < warp*16 + 16; ++li) {
            int gl = l0 + li;
            int s0 = g_soff[gl*(NT+1) + kt];
            int s1 = g_soff[gl*(NT+1) + kt + 1];
            float4 q0 = ((float4*)Qs)[li*16 + lg*2];
            float4 q1 = ((float4*)Qs)[li*16 + lg*2 + 1];
            float vmax = -CUDART_INF_F, vsum = 0.f;
            int nit = (s1 - s0 + 3) >> 2;
            for (int it = 0; it < nit; ++it) {
                int s = s0 + it*4 + grp;
                bool ok = s < s1;
                int j = ok ? g_sj[gl*SS + s] : kt*KT;
                int jj = j - kt*KT;
                const float* kr = Ks + jj*KPAD + lg*8;
                float4 k0 = *(const float4*)kr;
                float4 k1 = *(const float4*)(kr + 4);
                float p = q0.x*k0.x + q0.y*k0.y + q0.z*k0.z + q0.w*k0.w
                        + q1.x*k1.x + q1.y*k1.y + q1.z*k1.z + q1.w*k1.w;
                p += __shfl_xor_sync(0xffffffffu, p, 4);
                p += __shfl_xor_sync(0xffffffffu, p, 2);
                p += __shfl_xor_sync(0xffffffffu, p, 1);
                if (ok) { vmax = fmaxf(vmax, p); vsum += p; }
            }
            // combine the 4 groups (different samples, same l)
            vmax = fmaxf(vmax, __shfl_xor_sync(0xffffffffu, vmax, 8));
            vmax = fmaxf(vmax, __shfl_xor_sync(0xffffffffu, vmax, 16));
            vsum += __shfl_xor_sync(0xffffffffu, vsum, 8);
            vsum += __shfl_xor_sync(0xffffffffu, vsum, 16);
            if (lane == 0) { smax[li] = fmaxf(smax[li], vmax); ssum[li] += vsum; }
        }
        __syncthreads();
    }

    for (int i = t; i < LT; i += 256)
        g_M[bh*LL + l0 + i] = smax[i] - ssum[i] * (1.0f/(float)LL);
}

// ---------------------------------------------------------------------------
// Kernel 2: per-(b,h) top-80 via radix select + bitonic sort.
// Matches jax.lax.top_k exactly: values desc, ties -> ascending index, and
// tie-set at the cutoff takes smallest indices. Then winner replay.
// ---------------------------------------------------------------------------
__global__ void k_topk() {
    int bh = blockIdx.x, t = threadIdx.x;
    __shared__ unsigned su[LL];
    __shared__ int hist[256];
    __shared__ int scnt[2];
    __shared__ unsigned long long keys[128];
    __shared__ int eqbuf[256];
    __shared__ int cgt, ceq;
    __shared__ int stop[UU];
    __shared__ int win[UU];

    // orderable transform: monotone map float -> uint32
    for (int i = t; i < LL; i += 256) {
        unsigned bb = __float_as_uint(g_M[bh*LL + i]);
        su[i] = (bb & 0x80000000u) ? ~bb : (bb | 0x80000000u);
    }
    __syncthreads();

    // 4-pass byte radix: find T = 80th-largest value, need = #ties to take
    unsigned prefix = 0, prefmask = 0;
    int need = UU;
    for (int pass = 0; pass < 4; ++pass) {
        int shift = 24 - pass*8;
        hist[t] = 0;
        __syncthreads();
        for (int i = t; i < LL; i += 256) {
            unsigned u = su[i];
            if ((u & prefmask) == prefix) atomicAdd(&hist[(u >> shift) & 0xFF], 1);
        }
        __syncthreads();
        if (t == 0) {
            int acc = 0, bbin = 255;
            for (; bbin >= 0; --bbin) {
                if (acc + hist[bbin] >= need) break;
                acc += hist[bbin];
            }
            scnt[0] = bbin; scnt[1] = acc;
        }
        __syncthreads();
        prefix |= ((unsigned)scnt[0]) << shift;
        prefmask |= 0xFFu << shift;
        need -= scnt[1];
        __syncthreads();
    }
    unsigned T = prefix;

    // collect strictly-greater keys and tie indices
    if (t == 0) { cgt = 0; ceq = 0; }
    __syncthreads();
    for (int i = t; i < LL; i += 256) {
        unsigned u = su[i];
        if (u > T) {
            int p = atomicAdd(&cgt, 1);
            keys[p] = ((unsigned long long)u << 32) | (unsigned)(~i);
        } else if (u == T) {
            int p = atomicAdd(&ceq, 1);
            if (p < 256) eqbuf[p] = i;
        }
    }
    __syncthreads();
    if (t == 0) {
        int base = cgt;
        int ce = min(ceq, 256);
        for (int k = 0; k < need; ++k) {
            int mi = 0x7fffffff, mp = -1;
            for (int e = 0; e < ce; ++e)
                if (eqbuf[e] < mi) { mi = eqbuf[e]; mp = e; }
            keys[base + k] = ((unsigned long long)T << 32) | (unsigned)(~mi);
            eqbuf[mp] = 0x7fffffff;
        }
    }
    // pad to 128 (0 sorts last in descending order; real keys are nonzero)
    for (int i = t; i < 128; i += 256) if (i >= UU) keys[i] = 0ULL;
    __syncthreads();

    // bitonic sort, 128 elements, DESCENDING (=> value desc, index asc)
    for (int ksz = 2; ksz <= 128; ksz <<= 1) {
        for (int jst = ksz >> 1; jst > 0; jst >>= 1) {
            __syncthreads();
            if (t < 128) {
                int ixj = t ^ jst;
                if (ixj > t) {
                    unsigned long long a = keys[t], c = keys[ixj];
                    bool up = (t & ksz) == 0;
                    if (up ? (a < c) : (a > c)) { keys[t] = c; keys[ixj] = a; }
                }
            }
        }
    }
    __syncthreads();

    if (t < UU) {
        stop[t] = (int)(~(unsigned)(keys[t] & 0xffffffffu));
        win[t] = -1;
    }
    __syncthreads();
    if (t == 0) {
        for (int u = 0; u < UU; ++u) { int jj = min(stop[u], UU-1); win[jj] = u; }
        int n = 0;
        for (int jj = 0; jj < UU; ++jj) {
            if (win[jj] >= 0) {
                g_wl[bh*UU + n] = stop[win[jj]];
                g_wj[bh*UU + n] = jj;
                n++;
            }
        }
        g_nw[bh] = n;
    }
}

// ---------------------------------------------------------------------------
// Kernel 3a: V partial sums, grid (bh, VSPLIT)
// ---------------------------------------------------------------------------
__global__ void k_vpart(const float* __restrict__ V) {
    int bh = blockIdx.x, sp = blockIdx.y;
    int b = bh >> 3, h = bh & 7;
    int t = threadIdx.x, grp = t >> 6, d = t & 63;
    __shared__ float ac[4][64];
    int k0 = sp * VCHUNK;
    float s = 0.f;
    #pragma unroll 8
    for (int kk = grp; kk < VCHUNK; kk += 4)
        s += V[(((size_t)b*LL + k0 + kk)*HH + h)*DD + d];
    ac[grp][d] = s;
    __syncthreads();
    if (t < 64)
        g_vpart[(bh*VSPLIT + sp)*DD + t] = ac[0][t] + ac[1][t] + ac[2][t] + ac[3][t];
}

// ---------------------------------------------------------------------------
// Kernel 3b: combine V partials -> mean, broadcast-fill all 80 output rows
// ---------------------------------------------------------------------------
__global__ void k_fill(float* __restrict__ out) {
    int bh = blockIdx.x; int b = bh >> 3, h = bh & 7;
    int t = threadIdx.x;
    __shared__ float mean[64];
    if (t < 64) {
        float s = 0.f;
        #pragma unroll
        for (int i = 0; i < VSPLIT; ++i) s += g_vpart[(bh*VSPLIT + i)*DD + t];
        mean[t] = s * (1.0f/(float)LL);
    }
    __syncthreads();
    for (int e = t; e < UU*64; e += 256) {
        int j = e >> 6, d = e & 63;
        out[(((size_t)b*UU + j)*HH + h)*DD + d] = mean[d];
    }
}

// ---------------------------------------------------------------------------
// Kernel 4a: split-K attention partials for winner rows only
// ---------------------------------------------------------------------------
__global__ void k_attn_part(const float* __restrict__ Q, const float* __restrict__ K,
                            const float* __restrict__ V) {
    int bh = blockIdx.x;
    if ((int)blockIdx.y >= g_nw[bh]) return;
    int u = blockIdx.y, sp = blockIdx.z;
    int b = bh >> 3, h = bh & 7;
    int l = g_wl[bh*UU + u];
    int k0 = sp * CHUNK;

    __shared__ float q[DD];
    __shared__ float p[CHUNK];
    __shared__ float red[8];
    __shared__ float ac[4][64];
    int t = threadIdx.x, lane = t & 31, warp = t >> 5;

    if (t < DD) q[t] = Q[(((size_t)b*LL + l)*HH + h)*DD + t];
    __syncthreads();
    float q0 = q[lane*2], q1 = q[lane*2+1];

    float lmax = -CUDART_INF_F;
    #pragma unroll 4
    for (int kk = warp; kk < CHUNK; kk += 8) {
        float2 kv = *(const float2*)(K + (((size_t)b*LL + k0 + kk)*HH + h)*DD + lane*2);
        float s = q0*kv.x + q1*kv.y;
        #pragma unroll
        for (int o = 16; o; o >>= 1) s += __shfl_xor_sync(0xffffffffu, s, o);
        s *= 0.125f;
        if (lane == 0) p[kk] = s;
        lmax = fmaxf(lmax, s);
    }
    if (lane == 0) red[warp] = lmax;
    __syncthreads();
    if (t == 0) { float m = red[0]; for (int w = 1; w < 8; ++w) m = fmaxf(m, red[w]); red[0] = m; }
    __syncthreads();
    float m = red[0];
    __syncthreads();

    float ls = 0.f;
    if (t < CHUNK) { float e = __expf(p[t] - m); p[t] = e; ls = e; }
    #pragma unroll
    for (int o = 16; o; o >>= 1) ls += __shfl_xor_sync(0xffffffffu, ls, o);
    if (lane == 0) red[warp] = ls;
    __syncthreads();
    float ssumv = red[0]+red[1]+red[2]+red[3]+red[4]+red[5]+red[6]+red[7];

    int grp = t >> 6, d = t & 63;
    float acc = 0.f;
    #pragma unroll 8
    for (int kk = grp; kk < CHUNK; kk += 4)
        acc += p[kk] * V[(((size_t)b*LL + k0 + kk)*HH + h)*DD + d];
    ac[grp][d] = acc;
    __syncthreads();
    int base = (bh*UU + u)*SPLIT + sp;
    if (t < 64)
        g_pv[(size_t)base*DD + t] = ac[0][t] + ac[1][t] + ac[2][t] + ac[3][t];
    if (t == 0) { g_pmax[base] = m; g_psum[base] = ssumv; }
}

// ---------------------------------------------------------------------------
// Kernel 4b: combine split partials, normalize, write winner rows
// ---------------------------------------------------------------------------
__global__ void k_attn_comb(float* __restrict__ out) {
    int bh = blockIdx.x;
    if ((int)blockIdx.y >= g_nw[bh]) return;
    int u = blockIdx.y;
    int b = bh >> 3, h = bh & 7;
    int j = g_wj[bh*UU + u];
    int t = threadIdx.x;                 // 64 threads
    int base = (bh*UU + u)*SPLIT;

    float m = -CUDART_INF_F;
    #pragma unroll
    for (int i = 0; i < SPLIT; ++i) m = fmaxf(m, g_pmax[base + i]);
    float s = 0.f, pv = 0.f;
    #pragma unroll
    for (int i = 0; i < SPLIT; ++i) {
        float w = __expf(g_pmax[base + i] - m);
        s  += g_psum[base + i] * w;
        pv += g_pv[(size_t)(base + i)*DD + t] * w;
    }
    out[(((size_t)b*UU + j)*HH + h)*DD + t] = pv / s;
}

// ---------------------------------------------------------------------------
extern "C" void kernel_launch(void* const* d_in, const int* in_sizes, int n_in,
                              void* d_out, int out_size) {
    const float* Q   = (const float*)d_in[0];
    const float* K   = (const float*)d_in[1];
    const float* V   = (const float*)d_in[2];
    const int*   idx = (const int*)d_in[3];
    float* out = (float*)d_out;

    cudaFuncSetAttribute(k_sample2, cudaFuncAttributeMaxDynamicSharedMemorySize, SMP_SMEM);

    k_bucket<<<LL/256, 256>>>(idx);
    dim3 gs(LL/LT, BHN);
    k_sample2<<<gs, 256, SMP_SMEM>>>(Q, K);
    k_topk<<<BHN, 256>>>();
    dim3 gv(BHN, VSPLIT);
    k_vpart<<<gv, 256>>>(V);
    k_fill<<<BHN, 256>>>(out);
    dim3 ga(BHN, UU, SPLIT);
    k_attn_part<<<ga, 256>>>(Q, K, V);
    dim3 gc(BHN, UU);
    k_attn_comb<<<gc, 64>>>(out);
}

// round 4
// speedup vs baseline: 2.6946x; 2.6946x over previous
#include <cuda_runtime.h>
#include <cuda_bf16.h>
#include <math_constants.h>

// Problem constants (fixed by the benchmark)
#define BB 2
#define LL 2048
#define HH 8
#define DD 64
#define UU 80
#define SS 80
#define BHN (BB*HH)
#define SPLIT 8
#define CHUNK (LL/SPLIT)      // 256 keys per split block
#define UST 8                 // u-stride for winner loop

// Scratch (device globals; zero-initialized at module load)
__device__ float g_M[BB*HH*LL];           // sparsity measure M[b,h,l]
__device__ float g_vmean[BHN*DD];         // V column sums (atomic), zeroed after use
__device__ int   g_nw[BHN];               // winners per (b,h)
__device__ int   g_wl[BHN*UU];            // winner: source token l
__device__ int   g_wj[BHN*UU];            // winner: output slot j
__device__ float g_pmax[BHN*UU*SPLIT];    // split-softmax partial max
__device__ float g_psum[BHN*UU*SPLIT];    // split-softmax partial sum(exp)
__device__ float g_pv  [BHN*UU*SPLIT*DD]; // split partial (unnormalized) PV

// ---------------------------------------------------------------------------
// Kernel 1: sampled scores -> M[b,h,l], fused with V column sums.
// One warp per (b,h,l); 4 groups of 8 lanes, one sampled dot per group/iter.
// Each warp also reads its own V row; block reduces 8 rows and atomically
// accumulates into g_vmean[bh]. All 8 warps of a block share the same bh.
// ---------------------------------------------------------------------------
__global__ void k_sample(const float* __restrict__ Q, const float* __restrict__ K,
                         const float* __restrict__ V, const int* __restrict__ idx) {
    __shared__ float sv[8][64];
    int t = threadIdx.x, lane = t & 31, warp = t >> 5;
    int gw = blockIdx.x * 8 + warp;
    int l  = gw & (LL-1);
    int bh = gw >> 11;
    int b = bh >> 3, h = bh & 7;
    int grp = lane >> 3, lg = lane & 7;

    const float* qrow = Q + (((size_t)b*LL + l)*HH + h)*DD;
    float4 q0 = *(const float4*)(qrow + lg*8);
    float4 q1 = *(const float4*)(qrow + lg*8 + 4);

    // V row for this l (coalesced float2 per lane)
    float2 vv = *(const float2*)(V + (((size_t)b*LL + l)*HH + h)*DD + lane*2);
    sv[warp][lane*2] = vv.x; sv[warp][lane*2+1] = vv.y;

    const int* irow = idx + l*SS;
    float vmax = -CUDART_INF_F, vsum = 0.f;

    #pragma unroll 5
    for (int it = 0; it < SS/4; ++it) {
        int j = irow[it*4 + grp];
        const float* krow = K + (((size_t)b*LL + j)*HH + h)*DD + lg*8;
        float4 k0 = *(const float4*)(krow);
        float4 k1 = *(const float4*)(krow + 4);
        float p = q0.x*k0.x + q0.y*k0.y + q0.z*k0.z + q0.w*k0.w
                + q1.x*k1.x + q1.y*k1.y + q1.z*k1.z + q1.w*k1.w;
        p += __shfl_xor_sync(0xffffffffu, p, 4);
        p += __shfl_xor_sync(0xffffffffu, p, 2);
        p += __shfl_xor_sync(0xffffffffu, p, 1);
        vmax = fmaxf(vmax, p);
        vsum += p;
    }
    vmax = fmaxf(vmax, __shfl_xor_sync(0xffffffffu, vmax, 8));
    vmax = fmaxf(vmax, __shfl_xor_sync(0xffffffffu, vmax, 16));
    vsum += __shfl_xor_sync(0xffffffffu, vsum, 8);
    vsum += __shfl_xor_sync(0xffffffffu, vsum, 16);
    if (lane == 0) g_M[gw] = vmax - vsum * (1.0f/(float)LL);

    __syncthreads();
    if (t < 64) {
        float s = sv[0][t] + sv[1][t] + sv[2][t] + sv[3][t]
                + sv[4][t] + sv[5][t] + sv[6][t] + sv[7][t];
        atomicAdd(&g_vmean[bh*64 + t], s);
    }
}

// ---------------------------------------------------------------------------
// Kernel 2: per-(b,h) top-80 via radix select + bitonic sort (exact
// jax.lax.top_k semantics), winner replay, AND V_mean fill of all 80 output
// rows. Consumes g_vmean then re-zeroes it for the next graph replay.
// ---------------------------------------------------------------------------
__global__ void k_topk(float* __restrict__ out) {
    int bh = blockIdx.x, t = threadIdx.x;
    int b = bh >> 3, h = bh & 7;
    __shared__ unsigned su[LL];
    __shared__ int hist[256];
    __shared__ int scnt[2];
    __shared__ unsigned long long keys[128];
    __shared__ int eqbuf[256];
    __shared__ int cgt, ceq;
    __shared__ int stop[UU];
    __shared__ int win[UU];
    __shared__ float mean[64];

    // V mean (consume + reset scratch)
    if (t < 64) {
        mean[t] = g_vmean[bh*64 + t] * (1.0f/(float)LL);
        g_vmean[bh*64 + t] = 0.f;
    }

    // orderable transform: monotone map float -> uint32
    for (int i = t; i < LL; i += 256) {
        unsigned bb = __float_as_uint(g_M[bh*LL + i]);
        su[i] = (bb & 0x80000000u) ? ~bb : (bb | 0x80000000u);
    }
    __syncthreads();

    // broadcast-fill all 80 output rows with V_mean (overwritten for winners)
    for (int e = t; e < UU*64; e += 256) {
        int j = e >> 6, d = e & 63;
        out[(((size_t)b*UU + j)*HH + h)*DD + d] = mean[d];
    }

    // 4-pass byte radix: find T = 80th-largest transformed value
    unsigned prefix = 0, prefmask = 0;
    int need = UU;
    for (int pass = 0; pass < 4; ++pass) {
        int shift = 24 - pass*8;
        hist[t] = 0;
        __syncthreads();
        for (int i = t; i < LL; i += 256) {
            unsigned u = su[i];
            if ((u & prefmask) == prefix) atomicAdd(&hist[(u >> shift) & 0xFF], 1);
        }
        __syncthreads();
        if (t == 0) {
            int acc = 0, bbin = 255;
            for (; bbin >= 0; --bbin) {
                if (acc + hist[bbin] >= need) break;
                acc += hist[bbin];
            }
            scnt[0] = bbin; scnt[1] = acc;
        }
        __syncthreads();
        prefix |= ((unsigned)scnt[0]) << shift;
        prefmask |= 0xFFu << shift;
        need -= scnt[1];
        __syncthreads();
    }
    unsigned T = prefix;

    // collect strictly-greater keys and tie indices
    if (t == 0) { cgt = 0; ceq = 0; }
    __syncthreads();
    for (int i = t; i < LL; i += 256) {
        unsigned u = su[i];
        if (u > T) {
            int p = atomicAdd(&cgt, 1);
            keys[p] = ((unsigned long long)u << 32) | (unsigned)(~i);
        } else if (u == T) {
            int p = atomicAdd(&ceq, 1);
            if (p < 256) eqbuf[p] = i;
        }
    }
    __syncthreads();
    if (t == 0) {
        int base = cgt;
        int ce = min(ceq, 256);
        for (int k = 0; k < need; ++k) {
            int mi = 0x7fffffff, mp = -1;
            for (int e = 0; e < ce; ++e)
                if (eqbuf[e] < mi) { mi = eqbuf[e]; mp = e; }
            keys[base + k] = ((unsigned long long)T << 32) | (unsigned)(~mi);
            eqbuf[mp] = 0x7fffffff;
        }
    }
    for (int i = t; i < 128; i += 256) if (i >= UU) keys[i] = 0ULL;
    __syncthreads();

    // bitonic sort, 128 elements, descending (=> value desc, index asc)
    for (int ksz = 2; ksz <= 128; ksz <<= 1) {
        for (int jst = ksz >> 1; jst > 0; jst >>= 1) {
            __syncthreads();
            if (t < 128) {
                int ixj = t ^ jst;
                if (ixj > t) {
                    unsigned long long a = keys[t], c = keys[ixj];
                    bool up = (t & ksz) == 0;
                    if (up ? (a < c) : (a > c)) { keys[t] = c; keys[ixj] = a; }
                }
            }
        }
    }
    __syncthreads();

    if (t < UU) {
        stop[t] = (int)(~(unsigned)(keys[t] & 0xffffffffu));
        win[t] = -1;
    }
    __syncthreads();
    if (t == 0) {
        for (int u = 0; u < UU; ++u) { int jj = min(stop[u], UU-1); win[jj] = u; }
        int n = 0;
        for (int jj = 0; jj < UU; ++jj) {
            if (win[jj] >= 0) {
                g_wl[bh*UU + n] = stop[win[jj]];
                g_wj[bh*UU + n] = jj;
                n++;
            }
        }
        g_nw[bh] = n;
    }
}

// ---------------------------------------------------------------------------
// Kernel 3: split-K attention partials for winner rows.
// grid (bh, UST, SPLIT); block loops u += UST so any winner count is handled.
// Scores: 8-lane groups, 4 keys per warp-iteration (3 shfls per key-group).
// ---------------------------------------------------------------------------
__global__ void k_attn_part(const float* __restrict__ Q, const float* __restrict__ K,
                            const float* __restrict__ V) {
    int bh = blockIdx.x;
    int n = g_nw[bh];
    int b = bh >> 3, h = bh & 7;
    int sp = blockIdx.z, k0 = sp * CHUNK;

    __shared__ float q[DD];
    __shared__ float p[CHUNK];
    __shared__ float red[8];
    __shared__ float ac[4][64];
    int t = threadIdx.x, lane = t & 31, warp = t >> 5;
    int grp = lane >> 3, lg = lane & 7;

    for (int u = blockIdx.y; u < n; u += UST) {
        int l = g_wl[bh*UU + u];
        if (t < DD) q[t] = Q[(((size_t)b*LL + l)*HH + h)*DD + t];
        __syncthreads();
        float4 q0 = ((float4*)q)[lg*2];
        float4 q1 = ((float4*)q)[lg*2 + 1];

        // scores: warp owns 32 keys, 4 per iteration (one per 8-lane group)
        float lmax = -CUDART_INF_F;
        #pragma unroll
        for (int it = 0; it < 8; ++it) {
            int kk = warp*32 + it*4 + grp;
            const float* kr = K + (((size_t)b*LL + k0 + kk)*HH + h)*DD + lg*8;
            float4 k0v = *(const float4*)kr;
            float4 k1v = *(const float4*)(kr + 4);
            float s = q0.x*k0v.x + q0.y*k0v.y + q0.z*k0v.z + q0.w*k0v.w
                    + q1.x*k1v.x + q1.y*k1v.y + q1.z*k1v.z + q1.w*k1v.w;
            s += __shfl_xor_sync(0xffffffffu, s, 4);
            s += __shfl_xor_sync(0xffffffffu, s, 2);
            s += __shfl_xor_sync(0xffffffffu, s, 1);
            s *= 0.125f;                 // 1/sqrt(64)
            if (lg == 0) p[kk] = s;
            lmax = fmaxf(lmax, s);
        }
        lmax = fmaxf(lmax, __shfl_xor_sync(0xffffffffu, lmax, 8));
        lmax = fmaxf(lmax, __shfl_xor_sync(0xffffffffu, lmax, 16));
        if (lane == 0) red[warp] = lmax;
        __syncthreads();                 // publishes p[] and red[]
        if (t == 0) { float m = red[0]; for (int w = 1; w < 8; ++w) m = fmaxf(m, red[w]); red[0] = m; }
        __syncthreads();
        float m = red[0];
        __syncthreads();                 // all read red[0] before reuse

        float e = __expf(p[t] - m);      // CHUNK == blockDim
        p[t] = e;
        float ls = e;
        #pragma unroll
        for (int o = 16; o; o >>= 1) ls += __shfl_xor_sync(0xffffffffu, ls, o);
        if (lane == 0) red[warp] = ls;
        __syncthreads();                 // publishes exp'd p[] and warp sums
        float ssum = red[0]+red[1]+red[2]+red[3]+red[4]+red[5]+red[6]+red[7];

        // partial PV: 4 key-groups x 64 d-threads, coalesced V reads
        int g4 = t >> 6, d = t & 63;
        float acc = 0.f;
        #pragma unroll 8
        for (int kk = g4; kk < CHUNK; kk += 4)
            acc += p[kk] * V[(((size_t)b*LL + k0 + kk)*HH + h)*DD + d];
        ac[g4][d] = acc;
        __syncthreads();
        int base = (bh*UU + u)*SPLIT + sp;
        if (t < 64)
            g_pv[(size_t)base*DD + t] = ac[0][t] + ac[1][t] + ac[2][t] + ac[3][t];
        if (t == 0) { g_pmax[base] = m; g_psum[base] = ssum; }
        __syncthreads();                 // smem reuse across u iterations
    }
}

// ---------------------------------------------------------------------------
// Kernel 4: combine split partials (max-rescale), normalize, write winners.
// ---------------------------------------------------------------------------
__global__ void k_attn_comb(float* __restrict__ out) {
    int bh = blockIdx.x;
    int n = g_nw[bh];
    int b = bh >> 3, h = bh & 7;
    int t = threadIdx.x;                 // 64 threads

    for (int u = blockIdx.y; u < n; u += UST) {
        int j = g_wj[bh*UU + u];
        int base = (bh*UU + u)*SPLIT;

        float m = -CUDART_INF_F;
        #pragma unroll
        for (int i = 0; i < SPLIT; ++i) m = fmaxf(m, g_pmax[base + i]);
        float s = 0.f, pv = 0.f;
        #pragma unroll
        for (int i = 0; i < SPLIT; ++i) {
            float w = __expf(g_pmax[base + i] - m);
            s  += g_psum[base + i] * w;
            pv += g_pv[(size_t)(base + i)*DD + t] * w;
        }
        out[(((size_t)b*UU + j)*HH + h)*DD + t] = pv / s;
    }
}

// ---------------------------------------------------------------------------
extern "C" void kernel_launch(void* const* d_in, const int* in_sizes, int n_in,
                              void* d_out, int out_size) {
    const float* Q   = (const float*)d_in[0];
    const float* K   = (const float*)d_in[1];
    const float* V   = (const float*)d_in[2];
    const int*   idx = (const int*)d_in[3];
    float* out = (float*)d_out;

    k_sample<<<(BB*HH*LL)/8, 256>>>(Q, K, V, idx);
    k_topk<<<BHN, 256>>>(out);
    dim3 ga(BHN, UST, SPLIT);
    k_attn_part<<<ga, 256>>>(Q, K, V);
    dim3 gc(BHN, UST);
    k_attn_comb<<<gc, 64>>>(out);
}

// round 5
// speedup vs baseline: 2.8138x; 1.0442x over previous
#include <cuda_runtime.h>
#include <cuda_bf16.h>
#include <math_constants.h>

// Problem constants (fixed by the benchmark)
#define BB 2
#define LL 2048
#define HH 8
#define DD 64
#define UU 80
#define SS 80
#define BHN (BB*HH)
#define SPLIT 8
#define CHUNK (LL/SPLIT)      // 256 keys per split block
#define UST 8                 // u-stride for winner loop
#define BLKS_PER_BH 256       // k_sample blocks per (b,h)

// Scratch (device globals; zero-initialized at module load)
__device__ float g_M[BB*HH*LL];           // sparsity measure M[b,h,l]
__device__ float g_vmean[BHN*DD];         // V column sums (atomic), re-zeroed after use
__device__ int   g_cb[BHN];               // per-bh completion counter (self-reset)
__device__ int   g_cu[BHN*UU];            // per-(bh,u) split counter (self-reset)
__device__ int   g_nw[BHN];               // winners per (b,h)
__device__ int   g_wl[BHN*UU];            // winner: source token l
__device__ int   g_wj[BHN*UU];            // winner: output slot j
__device__ float g_pmax[BHN*UU*SPLIT];    // split-softmax partial max
__device__ float g_psum[BHN*UU*SPLIT];    // split-softmax partial sum(exp)
__device__ float g_pv  [BHN*UU*SPLIT*DD]; // split partial (unnormalized) PV

// ---------------------------------------------------------------------------
// Kernel 1: sampled scores -> M[b,h,l] fused with V column sums; the LAST
// block of each (b,h) (completion counter) then runs top-80 (radix select +
// bitonic, exact jax.lax.top_k semantics), winner replay, and V_mean fill.
// ---------------------------------------------------------------------------
__global__ void k_sample_topk(const float* __restrict__ Q, const float* __restrict__ K,
                              const float* __restrict__ V, const int* __restrict__ idx,
                              float* __restrict__ out) {
    __shared__ float sv[8][64];
    __shared__ int   isLast;
    // top-k shared state (only used by the last block per bh)
    __shared__ unsigned su[LL];
    __shared__ int hist[256];
    __shared__ int scnt[2];
    __shared__ unsigned long long keys[128];
    __shared__ int eqbuf[256];
    __shared__ int cgt, ceq;
    __shared__ int stop[UU];
    __shared__ int win[UU];
    __shared__ float mean[64];

    int t = threadIdx.x, lane = t & 31, warp = t >> 5;
    int gw = blockIdx.x * 8 + warp;
    int l  = gw & (LL-1);
    int bh = gw >> 11;
    int b = bh >> 3, h = bh & 7;
    int grp = lane >> 3, lg = lane & 7;

    const float* qrow = Q + (((size_t)b*LL + l)*HH + h)*DD;
    float4 q0 = *(const float4*)(qrow + lg*8);
    float4 q1 = *(const float4*)(qrow + lg*8 + 4);

    // V row for this l (coalesced float2 per lane)
    float2 vv = *(const float2*)(V + (((size_t)b*LL + l)*HH + h)*DD + lane*2);
    sv[warp][lane*2] = vv.x; sv[warp][lane*2+1] = vv.y;

    const int* irow = idx + l*SS;
    float vmax = -CUDART_INF_F, vsum = 0.f;

    #pragma unroll 5
    for (int it = 0; it < SS/4; ++it) {
        int j = irow[it*4 + grp];
        const float* krow = K + (((size_t)b*LL + j)*HH + h)*DD + lg*8;
        float4 k0 = *(const float4*)(krow);
        float4 k1 = *(const float4*)(krow + 4);
        float p = q0.x*k0.x + q0.y*k0.y + q0.z*k0.z + q0.w*k0.w
                + q1.x*k1.x + q1.y*k1.y + q1.z*k1.z + q1.w*k1.w;
        p += __shfl_xor_sync(0xffffffffu, p, 4);
        p += __shfl_xor_sync(0xffffffffu, p, 2);
        p += __shfl_xor_sync(0xffffffffu, p, 1);
        vmax = fmaxf(vmax, p);
        vsum += p;
    }
    vmax = fmaxf(vmax, __shfl_xor_sync(0xffffffffu, vmax, 8));
    vmax = fmaxf(vmax, __shfl_xor_sync(0xffffffffu, vmax, 16));
    vsum += __shfl_xor_sync(0xffffffffu, vsum, 8);
    vsum += __shfl_xor_sync(0xffffffffu, vsum, 16);
    if (lane == 0) g_M[gw] = vmax - vsum * (1.0f/(float)LL);

    __syncthreads();
    if (t < 64) {
        float s = sv[0][t] + sv[1][t] + sv[2][t] + sv[3][t]
                + sv[4][t] + sv[5][t] + sv[6][t] + sv[7][t];
        atomicAdd(&g_vmean[bh*64 + t], s);
    }

    // ---- completion protocol: last block of this bh runs top-k inline ----
    __threadfence();
    __syncthreads();
    if (t == 0) {
        int old = atomicAdd(&g_cb[bh], 1);
        isLast = (old == BLKS_PER_BH - 1);
    }
    __syncthreads();
    if (!isLast) return;
    if (t == 0) g_cb[bh] = 0;    // self-reset for next graph replay

    // ======================= top-k body (last block) =======================
    // V mean (consume + reset scratch)
    if (t < 64) {
        mean[t] = g_vmean[bh*64 + t] * (1.0f/(float)LL);
        g_vmean[bh*64 + t] = 0.f;
    }

    // orderable transform: monotone map float -> uint32
    for (int i = t; i < LL; i += 256) {
        unsigned bb = __float_as_uint(g_M[bh*LL + i]);
        su[i] = (bb & 0x80000000u) ? ~bb : (bb | 0x80000000u);
    }
    __syncthreads();

    // broadcast-fill all 80 output rows with V_mean (winners overwritten later)
    for (int e = t; e < UU*64; e += 256) {
        int j = e >> 6, d = e & 63;
        out[(((size_t)b*UU + j)*HH + h)*DD + d] = mean[d];
    }

    // 4-pass byte radix: find T = 80th-largest transformed value
    unsigned prefix = 0, prefmask = 0;
    int need = UU;
    for (int pass = 0; pass < 4; ++pass) {
        int shift = 24 - pass*8;
        hist[t] = 0;
        __syncthreads();
        for (int i = t; i < LL; i += 256) {
            unsigned u = su[i];
            if ((u & prefmask) == prefix) atomicAdd(&hist[(u >> shift) & 0xFF], 1);
        }
        __syncthreads();
        // warp-parallel descending bin scan (lane L owns bins 255-8L .. 248-8L)
        if (t < 32) {
            int base = 255 - t*8;
            int s = 0;
            #pragma unroll
            for (int e = 0; e < 8; ++e) s += hist[base - e];
            int pre = s;
            #pragma unroll
            for (int o = 1; o < 32; o <<= 1) {
                int v = __shfl_up_sync(0xffffffffu, pre, o);
                if (lane >= o) pre += v;
            }
            int excl = pre - s;      // count in bins above this chunk
            if (excl < need && need <= pre) {
                int acc = excl;
                #pragma unroll
                for (int e = 0; e < 8; ++e) {
                    int hb = hist[base - e];
                    if (acc + hb >= need) { scnt[0] = base - e; scnt[1] = acc; break; }
                    acc += hb;
                }
            }
        }
        __syncthreads();
        prefix |= ((unsigned)scnt[0]) << shift;
        prefmask |= 0xFFu << shift;
        need -= scnt[1];
        __syncthreads();
    }
    unsigned T = prefix;

    // collect strictly-greater keys and tie indices
    if (t == 0) { cgt = 0; ceq = 0; }
    __syncthreads();
    for (int i = t; i < LL; i += 256) {
        unsigned u = su[i];
        if (u > T) {
            int p = atomicAdd(&cgt, 1);
            keys[p] = ((unsigned long long)u << 32) | (unsigned)(~i);
        } else if (u == T) {
            int p = atomicAdd(&ceq, 1);
            if (p < 256) eqbuf[p] = i;
        }
    }
    __syncthreads();
    if (t == 0) {
        int base = cgt;
        int ce = min(ceq, 256);
        for (int k = 0; k < need; ++k) {
            int mi = 0x7fffffff, mp = -1;
            for (int e = 0; e < ce; ++e)
                if (eqbuf[e] < mi) { mi = eqbuf[e]; mp = e; }
            keys[base + k] = ((unsigned long long)T << 32) | (unsigned)(~mi);
            eqbuf[mp] = 0x7fffffff;
        }
    }
    for (int i = t; i < 128; i += 256) if (i >= UU) keys[i] = 0ULL;
    __syncthreads();

    // bitonic sort, 128 elements, descending (=> value desc, index asc)
    for (int ksz = 2; ksz <= 128; ksz <<= 1) {
        for (int jst = ksz >> 1; jst > 0; jst >>= 1) {
            __syncthreads();
            if (t < 128) {
                int ixj = t ^ jst;
                if (ixj > t) {
                    unsigned long long a = keys[t], c = keys[ixj];
                    bool up = (t & ksz) == 0;
                    if (up ? (a < c) : (a > c)) { keys[t] = c; keys[ixj] = a; }
                }
            }
        }
    }
    __syncthreads();

    if (t < UU) {
        stop[t] = (int)(~(unsigned)(keys[t] & 0xffffffffu));
        win[t] = -1;
    }
    __syncthreads();
    if (t == 0) {
        for (int u = 0; u < UU; ++u) { int jj = min(stop[u], UU-1); win[jj] = u; }
        int n = 0;
        for (int jj = 0; jj < UU; ++jj) {
            if (win[jj] >= 0) {
                g_wl[bh*UU + n] = stop[win[jj]];
                g_wj[bh*UU + n] = jj;
                n++;
            }
        }
        g_nw[bh] = n;
    }
}

// ---------------------------------------------------------------------------
// Kernel 2: split-K attention partials for winner rows, with LAST-split-block
// combine (per-(bh,u) counter): max-rescale the 8 partials, normalize, write.
// grid (bh, UST, SPLIT); block loops u += UST.
// ---------------------------------------------------------------------------
__global__ void k_attn(const float* __restrict__ Q, const float* __restrict__ K,
                       const float* __restrict__ V, float* __restrict__ out) {
    int bh = blockIdx.x;
    int n = g_nw[bh];
    int b = bh >> 3, h = bh & 7;
    int sp = blockIdx.z, k0 = sp * CHUNK;

    __shared__ float q[DD];
    __shared__ float p[CHUNK];
    __shared__ float red[8];
    __shared__ float ac[4][64];
    __shared__ int lastf;
    int t = threadIdx.x, lane = t & 31, warp = t >> 5;
    int grp = lane >> 3, lg = lane & 7;

    for (int u = blockIdx.y; u < n; u += UST) {
        int l = g_wl[bh*UU + u];
        if (t < DD) q[t] = Q[(((size_t)b*LL + l)*HH + h)*DD + t];
        __syncthreads();
        float4 q0 = ((float4*)q)[lg*2];
        float4 q1 = ((float4*)q)[lg*2 + 1];

        // scores: warp owns 32 keys, 4 per iteration (one per 8-lane group)
        float lmax = -CUDART_INF_F;
        #pragma unroll
        for (int it = 0; it < 8; ++it) {
            int kk = warp*32 + it*4 + grp;
            const float* kr = K + (((size_t)b*LL + k0 + kk)*HH + h)*DD + lg*8;
            float4 k0v = *(const float4*)kr;
            float4 k1v = *(const float4*)(kr + 4);
            float s = q0.x*k0v.x + q0.y*k0v.y + q0.z*k0v.z + q0.w*k0v.w
                    + q1.x*k1v.x + q1.y*k1v.y + q1.z*k1v.z + q1.w*k1v.w;
            s += __shfl_xor_sync(0xffffffffu, s, 4);
            s += __shfl_xor_sync(0xffffffffu, s, 2);
            s += __shfl_xor_sync(0xffffffffu, s, 1);
            s *= 0.125f;                 // 1/sqrt(64)
            if (lg == 0) p[kk] = s;
            lmax = fmaxf(lmax, s);
        }
        lmax = fmaxf(lmax, __shfl_xor_sync(0xffffffffu, lmax, 8));
        lmax = fmaxf(lmax, __shfl_xor_sync(0xffffffffu, lmax, 16));
        if (lane == 0) red[warp] = lmax;
        __syncthreads();
        if (t == 0) { float m = red[0]; for (int w = 1; w < 8; ++w) m = fmaxf(m, red[w]); red[0] = m; }
        __syncthreads();
        float m = red[0];
        __syncthreads();

        float e = __expf(p[t] - m);      // CHUNK == blockDim
        p[t] = e;
        float ls = e;
        #pragma unroll
        for (int o = 16; o; o >>= 1) ls += __shfl_xor_sync(0xffffffffu, ls, o);
        if (lane == 0) red[warp] = ls;
        __syncthreads();
        float ssum = red[0]+red[1]+red[2]+red[3]+red[4]+red[5]+red[6]+red[7];

        // partial PV: 4 key-groups x 64 d-threads, coalesced V reads
        int g4 = t >> 6, d = t & 63;
        float acc = 0.f;
        #pragma unroll 8
        for (int kk = g4; kk < CHUNK; kk += 4)
            acc += p[kk] * V[(((size_t)b*LL + k0 + kk)*HH + h)*DD + d];
        ac[g4][d] = acc;
        __syncthreads();
        int base = (bh*UU + u)*SPLIT + sp;
        if (t < 64)
            g_pv[(size_t)base*DD + t] = ac[0][t] + ac[1][t] + ac[2][t] + ac[3][t];
        if (t == 0) { g_pmax[base] = m; g_psum[base] = ssum; }

        // ---- last split block for this (bh,u) combines and writes out ----
        __threadfence();
        __syncthreads();
        if (t == 0) {
            int old = atomicAdd(&g_cu[bh*UU + u], 1);
            lastf = (old == SPLIT - 1);
        }
        __syncthreads();
        if (lastf) {
            if (t == 0) g_cu[bh*UU + u] = 0;   // self-reset for replay
            if (t < 64) {
                int cb = (bh*UU + u)*SPLIT;
                float mm = -CUDART_INF_F;
                #pragma unroll
                for (int i = 0; i < SPLIT; ++i) mm = fmaxf(mm, g_pmax[cb + i]);
                float s = 0.f, pv = 0.f;
                #pragma unroll
                for (int i = 0; i < SPLIT; ++i) {
                    float w = __expf(g_pmax[cb + i] - mm);
                    s  += g_psum[cb + i] * w;
                    pv += g_pv[(size_t)(cb + i)*DD + t] * w;
                }
                int j = g_wj[bh*UU + u];
                out[(((size_t)b*UU + j)*HH + h)*DD + t] = pv / s;
            }
        }
        __syncthreads();                 // smem reuse across u iterations
    }
}

// ---------------------------------------------------------------------------
extern "C" void kernel_launch(void* const* d_in, const int* in_sizes, int n_in,
                              void* d_out, int out_size) {
    const float* Q   = (const float*)d_in[0];
    const float* K   = (const float*)d_in[1];
    const float* V   = (const float*)d_in[2];
    const int*   idx = (const int*)d_in[3];
    float* out = (float*)d_out;

    k_sample_topk<<<(BB*HH*LL)/8, 256>>>(Q, K, V, idx, out);
    dim3 ga(BHN, UST, SPLIT);
    k_attn<<<ga, 256>>>(Q, K, V, out);
}